// round 2
// baseline (speedup 1.0000x reference)
#include <cuda_runtime.h>
#include <cstdint>

#define S_LEN 1024
#define CS 768
#define CZ 128
#define NH 24
#define HD 32
#define NB 2
#define NROWS (NB * S_LEN)      // 2048
#define EPS 1e-5f
#define NEG_INF (-1e9f)

// ---------------- scratch (device globals; no runtime allocation) ----------------
__device__ float g_emb[NB * 3 * CS];            // shift|scale|gate per batch
__device__ float g_bsn[NROWS * CS];             // adaLN-modulated bs
__device__ float g_q[NROWS * CS];
__device__ float g_k[NROWS * CS];
__device__ float g_v[NROWS * CS];
__device__ float g_ao[NROWS * CS];              // attention output (b,s,h*32+d)
__device__ float g_bias[(size_t)NH * S_LEN * S_LEN];  // 100.7 MB: zbias + maskbias, [h][i][j]
__device__ float g_wz2[CZ * NH];                // ln_z_w[c] * w_z[c][h]
__device__ float g_wsum[NH];                    // sum_c wz2[c][h]
__device__ float g_bias0[NH];                   // sum_c ln_z_b[c] * w_z[c][h]

// ---------------- tiny setup: fold ln_z scale/bias into w_z ----------------
__global__ void setup_wz_kernel(const float* __restrict__ lnw,
                                const float* __restrict__ lnb,
                                const float* __restrict__ wz) {
    int tid = threadIdx.x;  // 128
    for (int idx = tid; idx < CZ * NH; idx += 128) {
        int c = idx / NH;
        g_wz2[idx] = lnw[c] * wz[idx];
    }
    __syncthreads();
    if (tid < NH) {
        float s = 0.f, b0 = 0.f;
        for (int c = 0; c < CZ; c++) {
            s += g_wz2[c * NH + tid];
            b0 += lnb[c] * wz[c * NH + tid];
        }
        g_wsum[tid] = s;
        g_bias0[tid] = b0;
    }
}

// ---------------- adaLN embedding: silu(t) @ w_adaln + b_adaln ----------------
__global__ void emb_kernel(const float* __restrict__ t,
                           const float* __restrict__ w,
                           const float* __restrict__ ba) {
    __shared__ float st[CS];
    int b = blockIdx.x;
    int tid = threadIdx.x;  // 768
    float x = t[b * CS + tid];
    st[tid] = x / (1.f + __expf(-x));  // silu
    __syncthreads();
    float a0 = ba[tid], a1 = ba[CS + tid], a2 = ba[2 * CS + tid];
    for (int k = 0; k < CS; k++) {
        float sv = st[k];
        const float* wr = w + k * (3 * CS);
        a0 = fmaf(sv, wr[tid], a0);
        a1 = fmaf(sv, wr[CS + tid], a1);
        a2 = fmaf(sv, wr[2 * CS + tid], a2);
    }
    g_emb[b * 3 * CS + tid] = a0;            // shift
    g_emb[b * 3 * CS + CS + tid] = a1;       // scale
    g_emb[b * 3 * CS + 2 * CS + tid] = a2;   // gate
}

// ---------------- bs LayerNorm + adaLN modulate ----------------
__global__ void bsnorm_kernel(const float* __restrict__ bs) {
    int r = blockIdx.x;        // 0..2047
    int tid = threadIdx.x;     // 256
    int b = r >> 10;
    const float* x = bs + (size_t)r * CS;
    float v[3];
    float s = 0.f, s2 = 0.f;
#pragma unroll
    for (int k = 0; k < 3; k++) {
        v[k] = x[tid + k * 256];
        s += v[k];
        s2 = fmaf(v[k], v[k], s2);
    }
#pragma unroll
    for (int o = 16; o > 0; o >>= 1) {
        s += __shfl_xor_sync(0xffffffffu, s, o);
        s2 += __shfl_xor_sync(0xffffffffu, s2, o);
    }
    __shared__ float rs[8], rs2[8];
    int wid = tid >> 5, lane = tid & 31;
    if (lane == 0) { rs[wid] = s; rs2[wid] = s2; }
    __syncthreads();
    float S = 0.f, S2 = 0.f;
#pragma unroll
    for (int w = 0; w < 8; w++) { S += rs[w]; S2 += rs2[w]; }
    float mu = S * (1.f / CS);
    float var = S2 * (1.f / CS) - mu * mu;
    float rstd = rsqrtf(var + EPS);
    const float* eb = g_emb + b * 3 * CS;
#pragma unroll
    for (int k = 0; k < 3; k++) {
        int c = tid + k * 256;
        g_bsn[(size_t)r * CS + c] = (v[k] - mu) * rstd * (1.f + eb[CS + c]) + eb[c];
    }
}

// ---------------- generic 64x64 tiled fp32 GEMM (M=2048, N=768, K=768) ----------------
// mode 0/1/2: C = g_bsn @ W  -> g_q/g_k/g_v
// mode 3:     C = (g_ao @ W + bo) * gate  -> Cext
__global__ __launch_bounds__(256) void gemm_kernel(const float* __restrict__ W,
                                                   const float* __restrict__ bo,
                                                   float* __restrict__ Cext,
                                                   int mode) {
    const int M = NROWS, N = CS, K = CS;
    __shared__ float As[16][64];
    __shared__ float Bs[16][64];
    int tid = threadIdx.x;
    int tx = tid & 15, ty = tid >> 4;
    int row0 = blockIdx.y * 64;
    int col0 = blockIdx.x * 64;

    const float* A = (mode == 3) ? g_ao : g_bsn;
    float* C = (mode == 0) ? g_q : (mode == 1) ? g_k : (mode == 2) ? g_v : Cext;

    float acc[4][4];
#pragma unroll
    for (int i = 0; i < 4; i++)
#pragma unroll
        for (int j = 0; j < 4; j++) acc[i][j] = 0.f;

    int aRow = tid >> 2;
    int aK4 = (tid & 3) * 4;
    int bK = tid >> 4;
    int bC4 = (tid & 15) * 4;

    for (int k0 = 0; k0 < K; k0 += 16) {
        float4 av = *(const float4*)&A[(size_t)(row0 + aRow) * K + k0 + aK4];
        float4 bv = *(const float4*)&W[(size_t)(k0 + bK) * N + col0 + bC4];
        __syncthreads();
        As[aK4 + 0][aRow] = av.x;
        As[aK4 + 1][aRow] = av.y;
        As[aK4 + 2][aRow] = av.z;
        As[aK4 + 3][aRow] = av.w;
        *(float4*)&Bs[bK][bC4] = bv;
        __syncthreads();
#pragma unroll
        for (int k = 0; k < 16; k++) {
            float4 a = *(const float4*)&As[k][ty * 4];
            float4 bfr = *(const float4*)&Bs[k][tx * 4];
            float ar[4] = {a.x, a.y, a.z, a.w};
            float br[4] = {bfr.x, bfr.y, bfr.z, bfr.w};
#pragma unroll
            for (int i = 0; i < 4; i++)
#pragma unroll
                for (int j = 0; j < 4; j++) acc[i][j] = fmaf(ar[i], br[j], acc[i][j]);
        }
    }
    (void)M;
#pragma unroll
    for (int i = 0; i < 4; i++) {
        int row = row0 + ty * 4 + i;
        int col = col0 + tx * 4;
        float4 r = make_float4(acc[i][0], acc[i][1], acc[i][2], acc[i][3]);
        if (mode == 3) {
            const float* eb = g_emb + (row >> 10) * 3 * CS + 2 * CS;
            r.x = (r.x + bo[col + 0]) * eb[col + 0];
            r.y = (r.y + bo[col + 1]) * eb[col + 1];
            r.z = (r.z + bo[col + 2]) * eb[col + 2];
            r.w = (r.w + bo[col + 3]) * eb[col + 3];
        }
        *(float4*)&C[(size_t)row * N + col] = r;
    }
}

// ---------------- RMS norm over D=32 groups (q or k) ----------------
__global__ void rms_kernel(const float* __restrict__ w, int which) {
    int g = blockIdx.x * blockDim.x + threadIdx.x;  // 2048*24 groups
    if (g >= NROWS * NH) return;
    float* p = ((which == 0) ? g_q : g_k) + (size_t)g * HD;
    float4 v[8];
    float ss = 0.f;
#pragma unroll
    for (int e = 0; e < 8; e++) {
        v[e] = ((float4*)p)[e];
        ss = fmaf(v[e].x, v[e].x, ss);
        ss = fmaf(v[e].y, v[e].y, ss);
        ss = fmaf(v[e].z, v[e].z, ss);
        ss = fmaf(v[e].w, v[e].w, ss);
    }
    float r = rsqrtf(ss * (1.f / HD) + EPS);
#pragma unroll
    for (int e = 0; e < 8; e++) {
        v[e].x *= r * w[e * 4 + 0];
        v[e].y *= r * w[e * 4 + 1];
        v[e].z *= r * w[e * 4 + 2];
        v[e].w *= r * w[e * 4 + 3];
        ((float4*)p)[e] = v[e];
    }
}

// ---------------- z bias: LN(z) @ wz + mask, packed f32x2 FMA ----------------
// bias[h,i,j] = rinv*(P_h - mu*wsum_h) + bias0_h  (+ -1e9 where masked)
__global__ __launch_bounds__(256) void bias_kernel(const float* __restrict__ z,
                                                   const int* __restrict__ zmask) {
    __shared__ float swz[CZ * NH];   // [c][24]
    __shared__ float swsum[NH], sbias0[NH];
    int tid = threadIdx.x;
    for (int idx = tid; idx < CZ * NH; idx += 256) swz[idx] = g_wz2[idx];
    if (tid < NH) { swsum[tid] = g_wsum[tid]; sbias0[tid] = g_bias0[tid]; }
    __syncthreads();

    int p = blockIdx.x * 256 + tid;       // 0 .. 1M-1
    int i = p >> 10, j = p & 1023;
    int msk = zmask[p];

    unsigned long long acc[12];
#pragma unroll
    for (int q = 0; q < 12; q++) acc[q] = 0ULL;
    float s = 0.f, s2 = 0.f;

    if (msk) {
        const float4* zp = (const float4*)(z + ((size_t)p << 7));
#pragma unroll 2
        for (int c4 = 0; c4 < 32; c4++) {
            float4 zv = __ldg(&zp[c4]);
            float ze[4] = {zv.x, zv.y, zv.z, zv.w};
#pragma unroll
            for (int e = 0; e < 4; e++) {
                float zc = ze[e];
                s += zc;
                s2 = fmaf(zc, zc, s2);
                unsigned long long zz;
                asm("mov.b64 %0, {%1, %1};" : "=l"(zz) : "r"(__float_as_uint(zc)));
                const unsigned long long* wp =
                    (const unsigned long long*)(swz + (c4 * 4 + e) * NH);
#pragma unroll
                for (int q = 0; q < 12; q++) {
                    asm("fma.rn.f32x2 %0, %1, %2, %0;"
                        : "+l"(acc[q]) : "l"(zz), "l"(wp[q]));
                }
            }
        }
    }
    float mu = s * (1.f / CZ);
    float var = s2 * (1.f / CZ) - mu * mu;
    float rinv = rsqrtf(var + EPS);
    float* ob = g_bias + ((size_t)i << 10) + j;
#pragma unroll
    for (int q = 0; q < 12; q++) {
        unsigned lo, hi;
        asm("mov.b64 {%0, %1}, %2;" : "=r"(lo), "=r"(hi) : "l"(acc[q]));
        int h0 = 2 * q, h1 = 2 * q + 1;
        float v0 = rinv * (__uint_as_float(lo) - mu * swsum[h0]) + sbias0[h0];
        float v1 = rinv * (__uint_as_float(hi) - mu * swsum[h1]) + sbias0[h1];
        ob[(size_t)h0 << 20] = msk ? v0 : NEG_INF;
        ob[(size_t)h1 << 20] = msk ? v1 : NEG_INF;
    }
}

// ---------------- flash attention, fp32, thread = one query row ----------------
__global__ __launch_bounds__(128, 3) void attn_kernel(const float* __restrict__ beta) {
    __shared__ float ks[32][32];
    __shared__ float vs[32][32];
    int tid = threadIdx.x;            // 128
    int qt = blockIdx.x;              // 0..7
    int h = blockIdx.y;               // 0..23
    int b = blockIdx.z;               // 0..1
    int i = qt * 128 + tid;

    const float qscale = 0.17677669529663687f;  // 1/sqrt(32)
    float4 qv[8];
    const float4* qp = (const float4*)(g_q + (size_t)((b << 10) + i) * CS + h * HD);
#pragma unroll
    for (int e = 0; e < 8; e++) {
        qv[e] = qp[e];
        qv[e].x *= qscale; qv[e].y *= qscale; qv[e].z *= qscale; qv[e].w *= qscale;
    }
    float4 ov[8];
#pragma unroll
    for (int e = 0; e < 8; e++) ov[e] = make_float4(0.f, 0.f, 0.f, 0.f);
    float m = -1e30f, l = 0.f;

    const float* biasRow = g_bias + ((size_t)h << 20) + ((size_t)i << 10);
    const float* betaRow = beta + ((size_t)((b << 10) + i) << 10);

    int jj0 = tid >> 2;
    int e0 = tid & 3;

    for (int kt = 0; kt < 32; kt++) {
        int j0 = kt * 32;
        __syncthreads();
        {
            const float* kb = g_k + (size_t)((b << 10) + j0 + jj0) * CS + h * HD;
            const float* vb = g_v + (size_t)((b << 10) + j0 + jj0) * CS + h * HD;
            *(float4*)&ks[jj0][e0 * 4] = *(const float4*)(kb + e0 * 4);
            *(float4*)&ks[jj0][(e0 + 4) * 4] = *(const float4*)(kb + (e0 + 4) * 4);
            *(float4*)&vs[jj0][e0 * 4] = *(const float4*)(vb + e0 * 4);
            *(float4*)&vs[jj0][(e0 + 4) * 4] = *(const float4*)(vb + (e0 + 4) * 4);
        }
        __syncthreads();

        float sc[32];
#pragma unroll
        for (int e = 0; e < 8; e++) {
            float4 bb = *(const float4*)(biasRow + j0 + e * 4);
            float4 bt = *(const float4*)(betaRow + j0 + e * 4);
            sc[e * 4 + 0] = bb.x + bt.x;
            sc[e * 4 + 1] = bb.y + bt.y;
            sc[e * 4 + 2] = bb.z + bt.z;
            sc[e * 4 + 3] = bb.w + bt.w;
        }
#pragma unroll
        for (int jj = 0; jj < 32; jj++) {
            float a0 = 0.f, a1 = 0.f, a2 = 0.f, a3 = 0.f;
#pragma unroll
            for (int e = 0; e < 8; e++) {
                float4 kv = *(const float4*)&ks[jj][e * 4];
                a0 = fmaf(qv[e].x, kv.x, a0);
                a1 = fmaf(qv[e].y, kv.y, a1);
                a2 = fmaf(qv[e].z, kv.z, a2);
                a3 = fmaf(qv[e].w, kv.w, a3);
            }
            sc[jj] += (a0 + a1) + (a2 + a3);
        }
        float tm = sc[0];
#pragma unroll
        for (int jj = 1; jj < 32; jj++) tm = fmaxf(tm, sc[jj]);
        float mn = fmaxf(m, tm);
        float f = __expf(m - mn);
        l *= f;
#pragma unroll
        for (int e = 0; e < 8; e++) {
            ov[e].x *= f; ov[e].y *= f; ov[e].z *= f; ov[e].w *= f;
        }
#pragma unroll
        for (int jj = 0; jj < 32; jj++) {
            float pw = __expf(sc[jj] - mn);
            l += pw;
#pragma unroll
            for (int e = 0; e < 8; e++) {
                float4 vv = *(const float4*)&vs[jj][e * 4];
                ov[e].x = fmaf(pw, vv.x, ov[e].x);
                ov[e].y = fmaf(pw, vv.y, ov[e].y);
                ov[e].z = fmaf(pw, vv.z, ov[e].z);
                ov[e].w = fmaf(pw, vv.w, ov[e].w);
            }
        }
        m = mn;
    }
    float inv = 1.f / l;
    float4* op = (float4*)(g_ao + (size_t)((b << 10) + i) * CS + h * HD);
#pragma unroll
    for (int e = 0; e < 8; e++) {
        ov[e].x *= inv; ov[e].y *= inv; ov[e].z *= inv; ov[e].w *= inv;
        op[e] = ov[e];
    }
}

// ---------------- launch ----------------
extern "C" void kernel_launch(void* const* d_in, const int* in_sizes, int n_in,
                              void* d_out, int out_size) {
    (void)in_sizes; (void)n_in; (void)out_size;
    const float* bs      = (const float*)d_in[0];
    const float* z       = (const float*)d_in[1];
    const float* t       = (const float*)d_in[2];
    const float* beta    = (const float*)d_in[3];
    const int*   zmask   = (const int*)d_in[4];
    const float* w_adaln = (const float*)d_in[5];
    const float* b_adaln = (const float*)d_in[6];
    const float* ln_z_w  = (const float*)d_in[7];
    const float* ln_z_b  = (const float*)d_in[8];
    const float* w_q     = (const float*)d_in[9];
    const float* w_k     = (const float*)d_in[10];
    const float* w_v     = (const float*)d_in[11];
    const float* w_z     = (const float*)d_in[12];
    const float* rms_q_w = (const float*)d_in[13];
    const float* rms_k_w = (const float*)d_in[14];
    const float* w_o     = (const float*)d_in[15];
    const float* b_o     = (const float*)d_in[16];
    float* out = (float*)d_out;

    setup_wz_kernel<<<1, 128>>>(ln_z_w, ln_z_b, w_z);
    bias_kernel<<<(S_LEN * S_LEN) / 256, 256>>>(z, zmask);
    emb_kernel<<<NB, CS>>>(t, w_adaln, b_adaln);
    bsnorm_kernel<<<NROWS, 256>>>(bs);

    dim3 gg(CS / 64, NROWS / 64);  // 12 x 32
    gemm_kernel<<<gg, 256>>>(w_q, nullptr, nullptr, 0);
    gemm_kernel<<<gg, 256>>>(w_k, nullptr, nullptr, 1);
    gemm_kernel<<<gg, 256>>>(w_v, nullptr, nullptr, 2);

    rms_kernel<<<(NROWS * NH + 255) / 256, 256>>>(rms_q_w, 0);
    rms_kernel<<<(NROWS * NH + 255) / 256, 256>>>(rms_k_w, 1);

    attn_kernel<<<dim3(8, NH, NB), 128>>>(beta);

    gemm_kernel<<<gg, 256>>>(w_o, b_o, out, 3);
}